// round 1
// baseline (speedup 1.0000x reference)
#include <cuda_runtime.h>

// ---------------- problem constants ----------------
#define BB    64
#define NSEQ  1024
#define NTOK  100
#define DIMC  256
#define KDIM  16
#define NHEAD 8
#define DVAL  64
#define HKV   640     // NH*(KD+D)
#define KEFF  1312    // 512 (v) + 800 (attn); zero block dropped
#define PROJIN 1512
#define EPSV  1e-5f

// ---------------- scratch (device globals; no allocation allowed) ----------------
__device__ float g_q[NTOK * 128];                                  // (t, h*16+d)
__device__ float g_k[(size_t)BB * NSEQ * 128];                     // (bn, h*16+d)
__device__ float g_v[(size_t)BB * NSEQ * 512];                     // hardswish(v), (bn, h*64+d)
__device__ float g_attn[(size_t)BB * NHEAD * NTOK * NSEQ];         // hardswish(p), (b,h,t,n)

__device__ __forceinline__ float hswish(float y) {
    return y * fminf(fmaxf(y + 3.f, 0.f), 6.f) * (1.f / 6.f);
}

// ---------------- kernel 1: q projection + BN ----------------
__global__ void k_qproj(const float* __restrict__ text, const float* __restrict__ qw,
                        const float* __restrict__ qg, const float* __restrict__ qb,
                        const float* __restrict__ qm, const float* __restrict__ qv) {
    int o = blockIdx.x * blockDim.x + threadIdx.x;   // 0..12799
    if (o >= NTOK * 128) return;
    int t = o >> 7, c = o & 127;
    const float4* tr = (const float4*)(text + t * DIMC);
    const float4* wr = (const float4*)(qw + c * DIMC);
    float acc = 0.f;
#pragma unroll 16
    for (int k = 0; k < DIMC / 4; k++) {
        float4 a = tr[k], w = wr[k];
        acc += a.x * w.x + a.y * w.y + a.z * w.z + a.w * w.w;
    }
    float s = qg[c] * rsqrtf(qv[c] + EPSV);
    g_q[o] = (acc - qm[c]) * s + qb[c];
}

// ---------------- kernel 2: kv GEMM (65536x640 = x @ kv_w^T) + BN, split k / hswish(v) ----------------
__global__ __launch_bounds__(256) void k_kvgemm(
    const float* __restrict__ A, const float* __restrict__ W,
    const float* __restrict__ g, const float* __restrict__ bta,
    const float* __restrict__ mu, const float* __restrict__ var)
{
    __shared__ float As[8][128];
    __shared__ float Bs[8][128];
    const int m0 = blockIdx.y * 128;
    const int n0 = blockIdx.x * 128;
    const int tid = threadIdx.x;
    const int lr = tid >> 1;
    const int lk = (tid & 1) * 4;
    const int tx = tid & 15, ty = tid >> 4;
    float acc[8][8] = {};
    const float* Ab = A + (size_t)(m0 + lr) * DIMC + lk;
    const float* Wb = W + (size_t)(n0 + lr) * DIMC + lk;
    for (int kt = 0; kt < DIMC; kt += 8) {
        float4 av = *(const float4*)(Ab + kt);
        float4 bv = *(const float4*)(Wb + kt);
        As[lk + 0][lr] = av.x; As[lk + 1][lr] = av.y; As[lk + 2][lr] = av.z; As[lk + 3][lr] = av.w;
        Bs[lk + 0][lr] = bv.x; Bs[lk + 1][lr] = bv.y; Bs[lk + 2][lr] = bv.z; Bs[lk + 3][lr] = bv.w;
        __syncthreads();
#pragma unroll
        for (int k = 0; k < 8; k++) {
            float4 a0 = *(const float4*)&As[k][ty * 8];
            float4 a1 = *(const float4*)&As[k][ty * 8 + 4];
            float4 b0 = *(const float4*)&Bs[k][tx * 8];
            float4 b1 = *(const float4*)&Bs[k][tx * 8 + 4];
            float ar[8] = {a0.x, a0.y, a0.z, a0.w, a1.x, a1.y, a1.z, a1.w};
            float br[8] = {b0.x, b0.y, b0.z, b0.w, b1.x, b1.y, b1.z, b1.w};
#pragma unroll
            for (int i = 0; i < 8; i++)
#pragma unroll
                for (int j = 0; j < 8; j++) acc[i][j] += ar[i] * br[j];
        }
        __syncthreads();
    }
#pragma unroll
    for (int j = 0; j < 8; j++) {
        int col = n0 + tx * 8 + j;
        float s  = g[col] * rsqrtf(var[col] + EPSV);
        float mm = mu[col], bb = bta[col];
        int h = col / 80, r = col % 80;
#pragma unroll
        for (int i = 0; i < 8; i++) {
            int row = m0 + ty * 8 + i;
            float y = (acc[i][j] - mm) * s + bb;
            if (r < KDIM) {
                g_k[(size_t)row * 128 + h * 16 + r] = y;
            } else {
                g_v[(size_t)row * 512 + h * 64 + (r - KDIM)] = hswish(y);
            }
        }
    }
}

// ---------------- kernel 3: attention logits + bias + softmax + hswish ----------------
__global__ __launch_bounds__(1024) void k_attn(const float* __restrict__ biases) {
    const int h = blockIdx.x, b = blockIdx.y;
    const int tid = threadIdx.x;     // = n in [0,1024)
    __shared__ float qs[NTOK * 16];
    __shared__ float bias_s[3200];   // idx range: p2x*100 + |t-p2y| <= 31*100+99
    __shared__ float red[32];
    __shared__ float bcast;

    float kr[16];
    const float4* kp = (const float4*)(g_k + (size_t)(b * NSEQ + tid) * 128 + h * 16);
#pragma unroll
    for (int i = 0; i < 4; i++) {
        float4 v = kp[i];
        kr[i * 4] = v.x; kr[i * 4 + 1] = v.y; kr[i * 4 + 2] = v.z; kr[i * 4 + 3] = v.w;
    }
    for (int i = tid; i < NTOK * 16; i += 1024) qs[i] = g_q[(i >> 4) * 128 + h * 16 + (i & 15)];
    for (int i = tid; i < 3200; i += 1024) bias_s[i] = biases[h * 10000 + i];
    __syncthreads();

    const int p2x = tid >> 5, p2y = tid & 31;
    const int warp = tid >> 5, lane = tid & 31;
    float* outp = g_attn + ((size_t)(b * NHEAD + h) * NTOK) * NSEQ + tid;

    for (int t = 0; t < NTOK; t++) {
        float logit = 0.f;
#pragma unroll
        for (int d = 0; d < 16; d++) logit += qs[t * 16 + d] * kr[d];
        int dy = t - p2y; if (dy < 0) dy = -dy;
        logit = logit * 0.25f + bias_s[p2x * 100 + dy];

        // block max
        float m = logit;
#pragma unroll
        for (int o = 16; o > 0; o >>= 1) m = fmaxf(m, __shfl_xor_sync(0xffffffffu, m, o));
        if (lane == 0) red[warp] = m;
        __syncthreads();
        if (warp == 0) {
            float v = red[lane];
#pragma unroll
            for (int o = 16; o > 0; o >>= 1) v = fmaxf(v, __shfl_xor_sync(0xffffffffu, v, o));
            if (lane == 0) bcast = v;
        }
        __syncthreads();
        float gm = bcast;
        float e = __expf(logit - gm);

        // block sum
        float s = e;
#pragma unroll
        for (int o = 16; o > 0; o >>= 1) s += __shfl_xor_sync(0xffffffffu, s, o);
        if (lane == 0) red[warp] = s;    // red reads (warp0) all happened before prior barrier
        __syncthreads();
        if (warp == 0) {
            float v = red[lane];
#pragma unroll
            for (int o = 16; o > 0; o >>= 1) v += __shfl_xor_sync(0xffffffffu, v, o);
            if (lane == 0) bcast = v;
        }
        __syncthreads();
        float p = e / bcast;
        // hardswish of p in [0,1]: clip is a no-op upper side
        outp[(size_t)t * NSEQ] = p * (p + 3.f) * (1.f / 6.f);
        __syncthreads();   // protect red/bcast before next t
    }
}

// ---------------- kernel 4: proj GEMM (65536x1312 @ 256x1312^T) + BN ----------------
__global__ __launch_bounds__(256) void k_proj(
    const float* __restrict__ PW,
    const float* __restrict__ g, const float* __restrict__ bta,
    const float* __restrict__ mu, const float* __restrict__ var,
    float* __restrict__ out)
{
    __shared__ float As[8][128];
    __shared__ float Bs[8][128];
    const int m0 = blockIdx.y * 128;     // bn tile (rows share the same b)
    const int n0 = blockIdx.x * 128;     // output-col tile
    const int tid = threadIdx.x;
    const int tx = tid & 15, ty = tid >> 4;
    const int lr = tid >> 1, lk = (tid & 1) * 4;
    const int b = m0 >> 10;
    const int nbase = m0 & 1023;
    const int mm = tid & 127, kk0 = tid >> 7;
    float acc[8][8] = {};
    const float* Wb = PW + (size_t)(n0 + lr) * PROJIN + lk;
    const float* Vb = g_v + (size_t)(m0 + lr) * 512 + lk;
    const float* Aat = g_attn + (size_t)b * (NHEAD * NTOK * NSEQ) + nbase;

    for (int kt = 0; kt < KEFF; kt += 8) {
        float4 bv = *(const float4*)(Wb + kt);
        Bs[lk + 0][lr] = bv.x; Bs[lk + 1][lr] = bv.y; Bs[lk + 2][lr] = bv.z; Bs[lk + 3][lr] = bv.w;
        if (kt < 512) {
            float4 av = *(const float4*)(Vb + kt);
            As[lk + 0][lr] = av.x; As[lk + 1][lr] = av.y; As[lk + 2][lr] = av.z; As[lk + 3][lr] = av.w;
        } else {
            const float* base = Aat + (size_t)(kt - 512) * NSEQ + mm;
#pragma unroll
            for (int kk = kk0; kk < 8; kk += 2)
                As[kk][mm] = base[(size_t)kk * NSEQ];
        }
        __syncthreads();
#pragma unroll
        for (int k = 0; k < 8; k++) {
            float4 a0 = *(const float4*)&As[k][ty * 8];
            float4 a1 = *(const float4*)&As[k][ty * 8 + 4];
            float4 b0 = *(const float4*)&Bs[k][tx * 8];
            float4 b1 = *(const float4*)&Bs[k][tx * 8 + 4];
            float ar[8] = {a0.x, a0.y, a0.z, a0.w, a1.x, a1.y, a1.z, a1.w};
            float br[8] = {b0.x, b0.y, b0.z, b0.w, b1.x, b1.y, b1.z, b1.w};
#pragma unroll
            for (int i = 0; i < 8; i++)
#pragma unroll
                for (int j = 0; j < 8; j++) acc[i][j] += ar[i] * br[j];
        }
        __syncthreads();
    }
#pragma unroll
    for (int j = 0; j < 8; j++) {
        int col = n0 + tx * 8 + j;
        float s  = g[col] * rsqrtf(var[col] + EPSV);
        float mmu = mu[col], bb = bta[col];
#pragma unroll
        for (int i = 0; i < 8; i++) {
            int row = m0 + ty * 8 + i;
            out[(size_t)row * DIMC + col] = (acc[i][j] - mmu) * s + bb;
        }
    }
}

// ---------------- launch ----------------
extern "C" void kernel_launch(void* const* d_in, const int* in_sizes, int n_in,
                              void* d_out, int out_size) {
    const float* x      = (const float*)d_in[0];
    const float* text   = (const float*)d_in[1];
    const float* kv_w   = (const float*)d_in[2];
    const float* kv_g   = (const float*)d_in[3];
    const float* kv_b   = (const float*)d_in[4];
    const float* kv_m   = (const float*)d_in[5];
    const float* kv_v   = (const float*)d_in[6];
    const float* q_w    = (const float*)d_in[7];
    const float* q_g    = (const float*)d_in[8];
    const float* q_b    = (const float*)d_in[9];
    const float* q_m    = (const float*)d_in[10];
    const float* q_v    = (const float*)d_in[11];
    const float* proj_w = (const float*)d_in[12];
    const float* proj_g = (const float*)d_in[13];
    const float* proj_b = (const float*)d_in[14];
    const float* proj_m = (const float*)d_in[15];
    const float* proj_v = (const float*)d_in[16];
    const float* biases = (const float*)d_in[17];
    float* out = (float*)d_out;

    k_qproj<<<50, 256>>>(text, q_w, q_g, q_b, q_m, q_v);
    k_kvgemm<<<dim3(HKV / 128, (BB * NSEQ) / 128), 256>>>(x, kv_w, kv_g, kv_b, kv_m, kv_v);
    k_attn<<<dim3(NHEAD, BB), 1024>>>(biases);
    k_proj<<<dim3(2, (BB * NSEQ) / 128), 256>>>(proj_w, proj_g, proj_b, proj_m, proj_v, out);
}

// round 2
// speedup vs baseline: 1.2017x; 1.2017x over previous
#include <cuda_runtime.h>

// ---------------- problem constants ----------------
#define BB    64
#define NSEQ  1024
#define NTOK  100
#define DIMC  256
#define KDIM  16
#define NHEAD 8
#define DVAL  64
#define HKV   640     // NH*(KD+D)
#define KEFF  1312    // 512 (v) + 800 (attn); zero block dropped
#define PROJIN 1512
#define EPSV  1e-5f

// ---------------- scratch (device globals; no allocation allowed) ----------------
__device__ float g_q[NTOK * 128];                                  // (t, h*16+d)
__device__ float g_k[(size_t)BB * NSEQ * 128];                     // (bn, h*16+d)
__device__ float g_v[(size_t)BB * NSEQ * 512];                     // hardswish(v), (bn, h*64+d)
__device__ float g_attn[(size_t)BB * NHEAD * NTOK * NSEQ];         // hardswish(p), (b,h,t,n)

__device__ __forceinline__ float hswish(float y) {
    return y * fminf(fmaxf(y + 3.f, 0.f), 6.f) * (1.f / 6.f);
}

// packed fp32x2 helpers (sm_100+ PTX)
__device__ __forceinline__ void ffma2(unsigned long long& d, unsigned long long a, unsigned long long b) {
    asm("fma.rn.f32x2 %0, %1, %2, %0;" : "+l"(d) : "l"(a), "l"(b));
}
__device__ __forceinline__ unsigned long long pk2(float lo, float hi) {
    unsigned long long r;
    asm("mov.b64 %0, {%1, %2};" : "=l"(r) : "f"(lo), "f"(hi));
    return r;
}
__device__ __forceinline__ void upk2(float& lo, float& hi, unsigned long long v) {
    asm("mov.b64 {%0, %1}, %2;" : "=f"(lo), "=f"(hi) : "l"(v));
}

// ---------------- kernel 1: q projection + BN ----------------
__global__ void k_qproj(const float* __restrict__ text, const float* __restrict__ qw,
                        const float* __restrict__ qg, const float* __restrict__ qb,
                        const float* __restrict__ qm, const float* __restrict__ qv) {
    int o = blockIdx.x * blockDim.x + threadIdx.x;   // 0..12799
    if (o >= NTOK * 128) return;
    int t = o >> 7, c = o & 127;
    const float4* tr = (const float4*)(text + t * DIMC);
    const float4* wr = (const float4*)(qw + c * DIMC);
    float acc = 0.f;
#pragma unroll 16
    for (int k = 0; k < DIMC / 4; k++) {
        float4 a = tr[k], w = wr[k];
        acc += a.x * w.x + a.y * w.y + a.z * w.z + a.w * w.w;
    }
    float s = qg[c] * rsqrtf(qv[c] + EPSV);
    g_q[o] = (acc - qm[c]) * s + qb[c];
}

// ---------------- kernel 2: kv GEMM (65536x640 = x @ kv_w^T) + BN, split k / hswish(v) ----------------
__global__ __launch_bounds__(256) void k_kvgemm(
    const float* __restrict__ A, const float* __restrict__ W,
    const float* __restrict__ g, const float* __restrict__ bta,
    const float* __restrict__ mu, const float* __restrict__ var)
{
    __shared__ float As[16][128];
    __shared__ float Bs[16][128];
    const int m0 = blockIdx.y * 128;
    const int n0 = blockIdx.x * 128;
    const int tid = threadIdx.x;
    const int lr = tid >> 1;
    const int lk = (tid & 1) * 4;
    const int tx = tid & 15, ty = tid >> 4;
    unsigned long long acc[8][4] = {};
    const float* Ab = A + (size_t)(m0 + lr) * DIMC + lk;
    const float* Wb = W + (size_t)(n0 + lr) * DIMC + lk;
    for (int kt = 0; kt < DIMC; kt += 16) {
        float4 av0 = *(const float4*)(Ab + kt);
        float4 av1 = *(const float4*)(Ab + kt + 8);
        float4 bv0 = *(const float4*)(Wb + kt);
        float4 bv1 = *(const float4*)(Wb + kt + 8);
        As[lk + 0][lr] = av0.x; As[lk + 1][lr] = av0.y; As[lk + 2][lr] = av0.z; As[lk + 3][lr] = av0.w;
        As[lk + 8][lr] = av1.x; As[lk + 9][lr] = av1.y; As[lk + 10][lr] = av1.z; As[lk + 11][lr] = av1.w;
        Bs[lk + 0][lr] = bv0.x; Bs[lk + 1][lr] = bv0.y; Bs[lk + 2][lr] = bv0.z; Bs[lk + 3][lr] = bv0.w;
        Bs[lk + 8][lr] = bv1.x; Bs[lk + 9][lr] = bv1.y; Bs[lk + 10][lr] = bv1.z; Bs[lk + 11][lr] = bv1.w;
        __syncthreads();
#pragma unroll
        for (int k = 0; k < 16; k++) {
            float4 a0 = *(const float4*)&As[k][ty * 8];
            float4 a1 = *(const float4*)&As[k][ty * 8 + 4];
            float4 b0 = *(const float4*)&Bs[k][tx * 8];
            float4 b1 = *(const float4*)&Bs[k][tx * 8 + 4];
            unsigned long long bd0 = pk2(b0.x, b0.y), bd1 = pk2(b0.z, b0.w);
            unsigned long long bd2 = pk2(b1.x, b1.y), bd3 = pk2(b1.z, b1.w);
            float ar[8] = {a0.x, a0.y, a0.z, a0.w, a1.x, a1.y, a1.z, a1.w};
#pragma unroll
            for (int i = 0; i < 8; i++) {
                unsigned long long ad = pk2(ar[i], ar[i]);
                ffma2(acc[i][0], ad, bd0);
                ffma2(acc[i][1], ad, bd1);
                ffma2(acc[i][2], ad, bd2);
                ffma2(acc[i][3], ad, bd3);
            }
        }
        __syncthreads();
    }
#pragma unroll
    for (int j2 = 0; j2 < 4; j2++) {
        int c0 = n0 + tx * 8 + j2 * 2;
        int c1 = c0 + 1;
        float s0 = g[c0] * rsqrtf(var[c0] + EPSV), s1 = g[c1] * rsqrtf(var[c1] + EPSV);
        float m0v = mu[c0], m1v = mu[c1];
        float b0v = bta[c0], b1v = bta[c1];
        int h0 = c0 / 80, r0 = c0 % 80;
        int h1 = c1 / 80, r1 = c1 % 80;
#pragma unroll
        for (int i = 0; i < 8; i++) {
            int row = m0 + ty * 8 + i;
            float vlo, vhi;
            upk2(vlo, vhi, acc[i][j2]);
            float y0 = (vlo - m0v) * s0 + b0v;
            float y1 = (vhi - m1v) * s1 + b1v;
            if (r0 < KDIM) g_k[(size_t)row * 128 + h0 * 16 + r0] = y0;
            else           g_v[(size_t)row * 512 + h0 * 64 + (r0 - KDIM)] = hswish(y0);
            if (r1 < KDIM) g_k[(size_t)row * 128 + h1 * 16 + r1] = y1;
            else           g_v[(size_t)row * 512 + h1 * 64 + (r1 - KDIM)] = hswish(y1);
        }
    }
}

// ---------------- kernel 3: attention logits + bias + softmax + hswish ----------------
// No max-pass: logits are bounded (|logit| < ~30), exp is safe in fp32, and softmax
// is shift-invariant so the result matches the reference.
__global__ __launch_bounds__(1024) void k_attn(const float* __restrict__ biases) {
    const int h = blockIdx.x, b = blockIdx.y;
    const int tid = threadIdx.x;     // = n in [0,1024)
    __shared__ float qs[NTOK * 16];
    __shared__ float bias_s[3200];
    __shared__ float red[32 * 10];
    __shared__ float bcast[10];

    float kr[16];
    const float4* kp = (const float4*)(g_k + (size_t)(b * NSEQ + tid) * 128 + h * 16);
#pragma unroll
    for (int i = 0; i < 4; i++) {
        float4 v = kp[i];
        kr[i * 4] = v.x; kr[i * 4 + 1] = v.y; kr[i * 4 + 2] = v.z; kr[i * 4 + 3] = v.w;
    }
    for (int i = tid; i < NTOK * 16; i += 1024) qs[i] = g_q[(i >> 4) * 128 + h * 16 + (i & 15)];
    for (int i = tid; i < 3200; i += 1024) bias_s[i] = biases[h * 10000 + i];
    __syncthreads();

    const int p2x = tid >> 5, p2y = tid & 31;
    const int warp = tid >> 5, lane = tid & 31;
    float* outp = g_attn + ((size_t)(b * NHEAD + h) * NTOK) * NSEQ + tid;

    for (int t0 = 0; t0 < NTOK; t0 += 10) {
        float e[10];
#pragma unroll
        for (int c = 0; c < 10; c++) {
            int t = t0 + c;
            float logit = 0.f;
#pragma unroll
            for (int d = 0; d < 16; d++) logit += qs[t * 16 + d] * kr[d];
            int dy = t - p2y; if (dy < 0) dy = -dy;
            logit = logit * 0.25f + bias_s[p2x * 100 + dy];
            float ex = __expf(logit);
            e[c] = ex;
            float s = ex;
#pragma unroll
            for (int o = 16; o > 0; o >>= 1) s += __shfl_xor_sync(0xffffffffu, s, o);
            if (lane == 0) red[warp * 10 + c] = s;
        }
        __syncthreads();
        if (warp == 0) {
#pragma unroll
            for (int c = 0; c < 10; c++) {
                float v = red[lane * 10 + c];
#pragma unroll
                for (int o = 16; o > 0; o >>= 1) v += __shfl_xor_sync(0xffffffffu, v, o);
                if (lane == 0) bcast[c] = v;
            }
        }
        __syncthreads();
#pragma unroll
        for (int c = 0; c < 10; c++) {
            float p = e[c] * __frcp_rn(bcast[c]);
            outp[(size_t)(t0 + c) * NSEQ] = p * (p + 3.f) * (1.f / 6.f);
        }
        // no extra barrier needed: next chunk's red writes are ordered by the
        // next __syncthreads before warp0 reads them, and bcast is rewritten
        // only after that barrier, past all reads above.
    }
}

// ---------------- kernel 4: proj GEMM (65536x1312 @ 256x1312^T) + BN ----------------
__global__ __launch_bounds__(256) void k_proj(
    const float* __restrict__ PW,
    const float* __restrict__ g, const float* __restrict__ bta,
    const float* __restrict__ mu, const float* __restrict__ var,
    float* __restrict__ out)
{
    __shared__ float As[16][128];
    __shared__ float Bs[16][128];
    const int m0 = blockIdx.y * 128;     // bn tile (rows share the same b)
    const int n0 = blockIdx.x * 128;     // output-col tile
    const int tid = threadIdx.x;
    const int tx = tid & 15, ty = tid >> 4;
    const int lr = tid >> 1, lk = (tid & 1) * 4;
    const int b = m0 >> 10;
    const int nbase = m0 & 1023;
    const int mm = tid & 127, kk0 = tid >> 7;
    unsigned long long acc[8][4] = {};
    const float* Wb = PW + (size_t)(n0 + lr) * PROJIN + lk;
    const float* Vb = g_v + (size_t)(m0 + lr) * 512 + lk;
    const float* Aat = g_attn + (size_t)b * (NHEAD * NTOK * NSEQ) + nbase;

    for (int kt = 0; kt < KEFF; kt += 16) {
        float4 bv0 = *(const float4*)(Wb + kt);
        float4 bv1 = *(const float4*)(Wb + kt + 8);
        Bs[lk + 0][lr] = bv0.x; Bs[lk + 1][lr] = bv0.y; Bs[lk + 2][lr] = bv0.z; Bs[lk + 3][lr] = bv0.w;
        Bs[lk + 8][lr] = bv1.x; Bs[lk + 9][lr] = bv1.y; Bs[lk + 10][lr] = bv1.z; Bs[lk + 11][lr] = bv1.w;
        if (kt < 512) {
            float4 av0 = *(const float4*)(Vb + kt);
            float4 av1 = *(const float4*)(Vb + kt + 8);
            As[lk + 0][lr] = av0.x; As[lk + 1][lr] = av0.y; As[lk + 2][lr] = av0.z; As[lk + 3][lr] = av0.w;
            As[lk + 8][lr] = av1.x; As[lk + 9][lr] = av1.y; As[lk + 10][lr] = av1.z; As[lk + 11][lr] = av1.w;
        } else {
            const float* base = Aat + (size_t)(kt - 512) * NSEQ + mm;
#pragma unroll
            for (int kk = kk0; kk < 16; kk += 2)
                As[kk][mm] = base[(size_t)kk * NSEQ];
        }
        __syncthreads();
#pragma unroll
        for (int k = 0; k < 16; k++) {
            float4 a0 = *(const float4*)&As[k][ty * 8];
            float4 a1 = *(const float4*)&As[k][ty * 8 + 4];
            float4 b0 = *(const float4*)&Bs[k][tx * 8];
            float4 b1 = *(const float4*)&Bs[k][tx * 8 + 4];
            unsigned long long bd0 = pk2(b0.x, b0.y), bd1 = pk2(b0.z, b0.w);
            unsigned long long bd2 = pk2(b1.x, b1.y), bd3 = pk2(b1.z, b1.w);
            float ar[8] = {a0.x, a0.y, a0.z, a0.w, a1.x, a1.y, a1.z, a1.w};
#pragma unroll
            for (int i = 0; i < 8; i++) {
                unsigned long long ad = pk2(ar[i], ar[i]);
                ffma2(acc[i][0], ad, bd0);
                ffma2(acc[i][1], ad, bd1);
                ffma2(acc[i][2], ad, bd2);
                ffma2(acc[i][3], ad, bd3);
            }
        }
        __syncthreads();
    }
#pragma unroll
    for (int j2 = 0; j2 < 4; j2++) {
        int c0 = n0 + tx * 8 + j2 * 2;
        int c1 = c0 + 1;
        float s0 = g[c0] * rsqrtf(var[c0] + EPSV), s1 = g[c1] * rsqrtf(var[c1] + EPSV);
        float m0v = mu[c0], m1v = mu[c1];
        float b0v = bta[c0], b1v = bta[c1];
#pragma unroll
        for (int i = 0; i < 8; i++) {
            int row = m0 + ty * 8 + i;
            float vlo, vhi;
            upk2(vlo, vhi, acc[i][j2]);
            out[(size_t)row * DIMC + c0] = (vlo - m0v) * s0 + b0v;
            out[(size_t)row * DIMC + c1] = (vhi - m1v) * s1 + b1v;
        }
    }
}

// ---------------- launch ----------------
extern "C" void kernel_launch(void* const* d_in, const int* in_sizes, int n_in,
                              void* d_out, int out_size) {
    const float* x      = (const float*)d_in[0];
    const float* text   = (const float*)d_in[1];
    const float* kv_w   = (const float*)d_in[2];
    const float* kv_g   = (const float*)d_in[3];
    const float* kv_b   = (const float*)d_in[4];
    const float* kv_m   = (const float*)d_in[5];
    const float* kv_v   = (const float*)d_in[6];
    const float* q_w    = (const float*)d_in[7];
    const float* q_g    = (const float*)d_in[8];
    const float* q_b    = (const float*)d_in[9];
    const float* q_m    = (const float*)d_in[10];
    const float* q_v    = (const float*)d_in[11];
    const float* proj_w = (const float*)d_in[12];
    const float* proj_g = (const float*)d_in[13];
    const float* proj_b = (const float*)d_in[14];
    const float* proj_m = (const float*)d_in[15];
    const float* proj_v = (const float*)d_in[16];
    const float* biases = (const float*)d_in[17];
    float* out = (float*)d_out;

    k_qproj<<<50, 256>>>(text, q_w, q_g, q_b, q_m, q_v);
    k_kvgemm<<<dim3(HKV / 128, (BB * NSEQ) / 128), 256>>>(x, kv_w, kv_g, kv_b, kv_m, kv_v);
    k_attn<<<dim3(NHEAD, BB), 1024>>>(biases);
    k_proj<<<dim3(2, (BB * NSEQ) / 128), 256>>>(proj_w, proj_g, proj_b, proj_m, proj_v, out);
}

// round 5
// speedup vs baseline: 2.0159x; 1.6775x over previous
#include <cuda_runtime.h>
#include <cuda_bf16.h>
#include <cstdint>

// ---------------- problem constants ----------------
#define BB    64
#define NSEQ  1024
#define NTOK  100
#define DIMC  256
#define KDIM  16
#define NHEAD 8
#define HKV   640
#define PROJIN 1512
#define EPSV  1e-5f
#define MTOT  (BB*NSEQ)

// ---------------- scratch ----------------
__device__ float g_q[NTOK * 128];                                   // (t, h*16+d)
__device__ float g_k[(size_t)MTOT * 128];                           // fp32 (bn, h*16+d)
__device__ __nv_bfloat16 g_vh[(size_t)MTOT * 512];                  // hi of hswish(v)
__device__ __nv_bfloat16 g_vl[(size_t)MTOT * 512];                  // lo of hswish(v)
__device__ __nv_bfloat16 g_ah[(size_t)BB * NHEAD * NTOK * NSEQ];    // hi of hswish(p)
__device__ __nv_bfloat16 g_al[(size_t)BB * NHEAD * NTOK * NSEQ];    // lo of hswish(p)

__device__ __forceinline__ float hswish(float y) {
    return y * fminf(fmaxf(y + 3.f, 0.f), 6.f) * (1.f / 6.f);
}
__device__ __forceinline__ uint32_t smem_u32(const void* p) {
    uint32_t a;
    asm("{ .reg .u64 t; cvta.to.shared.u64 t, %1; cvt.u32.u64 %0, t; }" : "=r"(a) : "l"(p));
    return a;
}
// bf16 hi/lo split helpers
__device__ __forceinline__ void split4(float4 v, unsigned long long& H, unsigned long long& L) {
    float f[4] = {v.x, v.y, v.z, v.w};
    unsigned long long h = 0, l = 0;
#pragma unroll
    for (int i = 0; i < 4; i++) {
        __nv_bfloat16 hb = __float2bfloat16_rn(f[i]);
        float r = f[i] - __bfloat162float(hb);
        __nv_bfloat16 lb = __float2bfloat16_rn(r);
        h |= (unsigned long long)__bfloat16_as_ushort(hb) << (16 * i);
        l |= (unsigned long long)__bfloat16_as_ushort(lb) << (16 * i);
    }
    H = h; L = l;
}
__device__ __forceinline__ void splitbf(float y, unsigned short& hu, unsigned short& lu) {
    __nv_bfloat16 hb = __float2bfloat16_rn(y);
    float r = y - __bfloat162float(hb);
    __nv_bfloat16 lb = __float2bfloat16_rn(r);
    hu = __bfloat16_as_ushort(hb); lu = __bfloat16_as_ushort(lb);
}

// ---------------- warp-mma primitives (baseline PTX, sm_80+) ----------------
__device__ __forceinline__ void ldsm4(uint32_t addr, uint32_t* r) {
    asm volatile("ldmatrix.sync.aligned.m8n8.x4.shared.b16 {%0,%1,%2,%3}, [%4];"
                 : "=r"(r[0]), "=r"(r[1]), "=r"(r[2]), "=r"(r[3]) : "r"(addr));
}
__device__ __forceinline__ void mma16816(float* c, const uint32_t* a, uint32_t b0, uint32_t b1) {
    asm volatile("mma.sync.aligned.m16n8k16.row.col.f32.bf16.bf16.f32 "
                 "{%0,%1,%2,%3}, {%4,%5,%6,%7}, {%8,%9}, {%0,%1,%2,%3};"
                 : "+f"(c[0]), "+f"(c[1]), "+f"(c[2]), "+f"(c[3])
                 : "r"(a[0]), "r"(a[1]), "r"(a[2]), "r"(a[3]), "r"(b0), "r"(b1));
}

// SMEM tile geometry: row pitch 80B (conflict-free ldmatrix), 128 rows -> 10240 B/tile
#define PITCH 80
#define T_AH 0
#define T_AL 10240
#define T_BH 20480
#define T_BL 30720

// 3-term mma block over one k16 step for one warp (A frags preloaded)
#define MMA_STEP(ah0, ah1, al0, al1, ks)                                     \
    {                                                                        \
        _Pragma("unroll")                                                    \
        for (int np = 0; np < 4; np++) {                                     \
            uint32_t bh[4], bl[4];                                           \
            uint32_t boff = (uint32_t)((wn * 64 + np * 16 + brow) * PITCH + ((ks) + bcol) * 2); \
            ldsm4(s0 + T_BH + boff, bh);                                     \
            ldsm4(s0 + T_BL + boff, bl);                                     \
            mma16816(c[0][np * 2],     ah0, bh[0], bh[1]);                   \
            mma16816(c[1][np * 2],     ah1, bh[0], bh[1]);                   \
            mma16816(c[0][np * 2 + 1], ah0, bh[2], bh[3]);                   \
            mma16816(c[1][np * 2 + 1], ah1, bh[2], bh[3]);                   \
            mma16816(c[0][np * 2],     al0, bh[0], bh[1]);                   \
            mma16816(c[1][np * 2],     al1, bh[0], bh[1]);                   \
            mma16816(c[0][np * 2 + 1], al0, bh[2], bh[3]);                   \
            mma16816(c[1][np * 2 + 1], al1, bh[2], bh[3]);                   \
            mma16816(c[0][np * 2],     ah0, bl[0], bl[1]);                   \
            mma16816(c[1][np * 2],     ah1, bl[0], bl[1]);                   \
            mma16816(c[0][np * 2 + 1], ah0, bl[2], bl[3]);                   \
            mma16816(c[1][np * 2 + 1], ah1, bl[2], bl[3]);                   \
        }                                                                    \
    }

// ---------------- kernel 1: q projection + BN ----------------
__global__ void k_qproj(const float* __restrict__ text, const float* __restrict__ qw,
                        const float* __restrict__ qg, const float* __restrict__ qb,
                        const float* __restrict__ qm, const float* __restrict__ qv) {
    int o = blockIdx.x * blockDim.x + threadIdx.x;
    if (o >= NTOK * 128) return;
    int t = o >> 7, col = o & 127;
    const float4* tr = (const float4*)(text + t * DIMC);
    const float4* wr = (const float4*)(qw + col * DIMC);
    float acc = 0.f;
#pragma unroll 16
    for (int k = 0; k < DIMC / 4; k++) {
        float4 a = tr[k], w = wr[k];
        acc += a.x * w.x + a.y * w.y + a.z * w.z + a.w * w.w;
    }
    float s = qg[col] * rsqrtf(qv[col] + EPSV);
    g_q[o] = (acc - qm[col]) * s + qb[col];
}

// ---------------- kernel 2: kv GEMM (bf16 3-term mma.sync) ----------------
__global__ __launch_bounds__(256, 2) void k_kv_mma(
    const float* __restrict__ X, const float* __restrict__ W,
    const float* __restrict__ gg, const float* __restrict__ bta,
    const float* __restrict__ mmu, const float* __restrict__ vvr)
{
    __shared__ __align__(16) unsigned char sm[40960];
    const int tid = threadIdx.x, lane = tid & 31, wid = tid >> 5;
    const int m0 = blockIdx.y * 128, n0 = blockIdx.x * 128;
    const uint32_t s0 = smem_u32(sm);
    const int wm = wid >> 1, wn = wid & 1;
    const int arow = ((lane >> 3) & 1) * 8 + (lane & 7);
    const int acol = (lane >> 4) * 8;
    const int brow = (lane >> 4) * 8 + (lane & 7);
    const int bcol = ((lane >> 3) & 1) * 8;
    float c[2][8][4] = {};

    for (int kc = 0; kc < 8; kc++) {
        const int kb = kc * 32;
#pragma unroll
        for (int i = 0; i < 4; i++) {                 // A tile 128x32
            int item = tid + i * 256;
            int row = item >> 3, c4 = item & 7;
            float4 v = *(const float4*)(X + (size_t)(m0 + row) * DIMC + kb + c4 * 4);
            unsigned long long H, L; split4(v, H, L);
            *(unsigned long long*)(sm + T_AH + row * PITCH + c4 * 8) = H;
            *(unsigned long long*)(sm + T_AL + row * PITCH + c4 * 8) = L;
        }
#pragma unroll
        for (int i = 0; i < 4; i++) {                 // B tile 128x32
            int item = tid + i * 256;
            int row = item >> 3, c4 = item & 7;
            float4 v = *(const float4*)(W + (size_t)(n0 + row) * DIMC + kb + c4 * 4);
            unsigned long long H, L; split4(v, H, L);
            *(unsigned long long*)(sm + T_BH + row * PITCH + c4 * 8) = H;
            *(unsigned long long*)(sm + T_BL + row * PITCH + c4 * 8) = L;
        }
        __syncthreads();
#pragma unroll
        for (int ks = 0; ks < 32; ks += 16) {
            uint32_t ah0[4], ah1[4], al0[4], al1[4];
            uint32_t aoff = (uint32_t)((wm * 32 + arow) * PITCH + (ks + acol) * 2);
            ldsm4(s0 + T_AH + aoff, ah0);
            ldsm4(s0 + T_AH + aoff + 16 * PITCH, ah1);
            ldsm4(s0 + T_AL + aoff, al0);
            ldsm4(s0 + T_AL + aoff + 16 * PITCH, al1);
            MMA_STEP(ah0, ah1, al0, al1, ks);
        }
        __syncthreads();
    }

    // epilogue: BN, then k -> g_k fp32, v -> hswish -> split bf16
    unsigned short* VH = (unsigned short*)g_vh;
    unsigned short* VL = (unsigned short*)g_vl;
#pragma unroll
    for (int mi = 0; mi < 2; mi++) {
        int row = m0 + wm * 32 + mi * 16 + (lane >> 2);
#pragma unroll
        for (int ni = 0; ni < 8; ni++) {
            int col = n0 + wn * 64 + ni * 8 + (lane & 3) * 2;
#pragma unroll
            for (int cc = 0; cc < 2; cc++) {
                int cl = col + cc;
                float s = gg[cl] * rsqrtf(vvr[cl] + EPSV);
                float mu = mmu[cl], bb = bta[cl];
                int h = cl / 80, r = cl % 80;
                float y0 = (c[mi][ni][cc] - mu) * s + bb;
                float y1 = (c[mi][ni][cc + 2] - mu) * s + bb;
                if (r < KDIM) {
                    g_k[(size_t)row * 128 + h * 16 + r] = y0;
                    g_k[(size_t)(row + 8) * 128 + h * 16 + r] = y1;
                } else {
                    unsigned short hu, lu;
                    size_t i0 = (size_t)row * 512 + h * 64 + (r - KDIM);
                    size_t i1 = (size_t)(row + 8) * 512 + h * 64 + (r - KDIM);
                    splitbf(hswish(y0), hu, lu); VH[i0] = hu; VL[i0] = lu;
                    splitbf(hswish(y1), hu, lu); VH[i1] = hu; VL[i1] = lu;
                }
            }
        }
    }
}

// ---------------- kernel 3: attention logits + bias + softmax + hswish -> split bf16 ----------------
__global__ __launch_bounds__(1024) void k_attn(const float* __restrict__ biases) {
    const int h = blockIdx.x, b = blockIdx.y;
    const int tid = threadIdx.x;
    __shared__ float qs[NTOK * 16];
    __shared__ float bias_s[3200];
    __shared__ float red[32 * 10];
    __shared__ float bcast[10];

    float kr[16];
    const float4* kp = (const float4*)(g_k + (size_t)(b * NSEQ + tid) * 128 + h * 16);
#pragma unroll
    for (int i = 0; i < 4; i++) {
        float4 v = kp[i];
        kr[i * 4] = v.x; kr[i * 4 + 1] = v.y; kr[i * 4 + 2] = v.z; kr[i * 4 + 3] = v.w;
    }
    for (int i = tid; i < NTOK * 16; i += 1024) qs[i] = g_q[(i >> 4) * 128 + (i & 15) + h * 16];
    for (int i = tid; i < 3200; i += 1024) bias_s[i] = biases[h * 10000 + i];
    __syncthreads();

    const int p2x = tid >> 5, p2y = tid & 31;
    const int warp = tid >> 5, lane = tid & 31;
    size_t obase = ((size_t)(b * NHEAD + h) * NTOK) * NSEQ + tid;
    unsigned short* AH = (unsigned short*)g_ah;
    unsigned short* AL = (unsigned short*)g_al;

    for (int t0 = 0; t0 < NTOK; t0 += 10) {
        float e[10];
#pragma unroll
        for (int cch = 0; cch < 10; cch++) {
            int t = t0 + cch;
            float logit = 0.f;
#pragma unroll
            for (int d = 0; d < 16; d++) logit += qs[t * 16 + d] * kr[d];
            int dy = t - p2y; if (dy < 0) dy = -dy;
            logit = logit * 0.25f + bias_s[p2x * 100 + dy];
            float ex = __expf(logit);
            e[cch] = ex;
            float s = ex;
#pragma unroll
            for (int o = 16; o > 0; o >>= 1) s += __shfl_xor_sync(0xffffffffu, s, o);
            if (lane == 0) red[warp * 10 + cch] = s;
        }
        __syncthreads();
        if (warp == 0) {
#pragma unroll
            for (int cch = 0; cch < 10; cch++) {
                float v = red[lane * 10 + cch];
#pragma unroll
                for (int o = 16; o > 0; o >>= 1) v += __shfl_xor_sync(0xffffffffu, v, o);
                if (lane == 0) bcast[cch] = v;
            }
        }
        __syncthreads();
#pragma unroll
        for (int cch = 0; cch < 10; cch++) {
            float p = e[cch] * __frcp_rn(bcast[cch]);
            float y = p * (p + 3.f) * (1.f / 6.f);
            unsigned short hu, lu; splitbf(y, hu, lu);
            size_t idx = obase + (size_t)(t0 + cch) * NSEQ;
            AH[idx] = hu; AL[idx] = lu;
        }
    }
}

// ---------------- kernel 4: proj GEMM (bf16 3-term mma.sync, K=1312) ----------------
__global__ __launch_bounds__(256, 2) void k_proj_mma(
    const float* __restrict__ PW,
    const float* __restrict__ gg, const float* __restrict__ bta,
    const float* __restrict__ mmu, const float* __restrict__ vvr,
    float* __restrict__ out)
{
    __shared__ __align__(16) unsigned char sm[40960];
    const int tid = threadIdx.x, lane = tid & 31, wid = tid >> 5;
    const int m0 = blockIdx.y * 128, n0 = blockIdx.x * 128;
    const int b = m0 >> 10, nbase = m0 & 1023;
    const int rowbase = b * 800;
    const uint32_t s0 = smem_u32(sm);
    const int wm = wid >> 1, wn = wid & 1;
    const int arow = ((lane >> 3) & 1) * 8 + (lane & 7);
    const int acol = (lane >> 4) * 8;
    const int brow = (lane >> 4) * 8 + (lane & 7);
    const int bcol = ((lane >> 3) & 1) * 8;
    const unsigned short* GAH = (const unsigned short*)g_ah;
    const unsigned short* GAL = (const unsigned short*)g_al;
    float c[2][8][4] = {};

    for (int kc = 0; kc < 41; kc++) {
        const int kt = kc * 32;
        // ---- B tile: proj_w rows n0..n0+127 ----
#pragma unroll
        for (int i = 0; i < 4; i++) {
            int item = tid + i * 256;
            int row = item >> 3, c4 = item & 7;
            float4 v = *(const float4*)(PW + (size_t)(n0 + row) * PROJIN + kt + c4 * 4);
            unsigned long long H, L; split4(v, H, L);
            *(unsigned long long*)(sm + T_BH + row * PITCH + c4 * 8) = H;
            *(unsigned long long*)(sm + T_BL + row * PITCH + c4 * 8) = L;
        }
        // ---- A tile ----
        if (kt < 512) {
            // v features: pre-split bf16, contiguous copy
#pragma unroll
            for (int i = 0; i < 2; i++) {
                int item = tid + i * 256;
                int row = item >> 2, c8 = item & 3;
                size_t idx = (size_t)(m0 + row) * 512 + kt + c8 * 8;
                *(uint4*)(sm + T_AH + row * PITCH + c8 * 16) = *(const uint4*)(g_vh + idx);
                *(uint4*)(sm + T_AL + row * PITCH + c8 * 16) = *(const uint4*)(g_vl + idx);
            }
        } else {
            // attn features: pre-split bf16, coalesced read + 2B transpose into tile
            const int kloc = kt - 512;
#pragma unroll
            for (int i = 0; i < 8; i++) {
                int item = tid + i * 256;
                int krow = item >> 6, nn = (item & 63) * 2;
                size_t idx = (size_t)(rowbase + kloc + krow) * NSEQ + nbase + nn;
                uint32_t vh = *(const uint32_t*)(GAH + idx);
                uint32_t vl = *(const uint32_t*)(GAL + idx);
                *(unsigned short*)(sm + T_AH + nn * PITCH + krow * 2)       = (unsigned short)vh;
                *(unsigned short*)(sm + T_AH + (nn + 1) * PITCH + krow * 2) = (unsigned short)(vh >> 16);
                *(unsigned short*)(sm + T_AL + nn * PITCH + krow * 2)       = (unsigned short)vl;
                *(unsigned short*)(sm + T_AL + (nn + 1) * PITCH + krow * 2) = (unsigned short)(vl >> 16);
            }
        }
        __syncthreads();
#pragma unroll
        for (int ks = 0; ks < 32; ks += 16) {
            uint32_t ah0[4], ah1[4], al0[4], al1[4];
            uint32_t aoff = (uint32_t)((wm * 32 + arow) * PITCH + (ks + acol) * 2);
            ldsm4(s0 + T_AH + aoff, ah0);
            ldsm4(s0 + T_AH + aoff + 16 * PITCH, ah1);
            ldsm4(s0 + T_AL + aoff, al0);
            ldsm4(s0 + T_AL + aoff + 16 * PITCH, al1);
            MMA_STEP(ah0, ah1, al0, al1, ks);
        }
        __syncthreads();
    }

    // epilogue: BN -> out
#pragma unroll
    for (int mi = 0; mi < 2; mi++) {
        int row = m0 + wm * 32 + mi * 16 + (lane >> 2);
#pragma unroll
        for (int ni = 0; ni < 8; ni++) {
            int col = n0 + wn * 64 + ni * 8 + (lane & 3) * 2;
#pragma unroll
            for (int cc = 0; cc < 2; cc++) {
                int cl = col + cc;
                float s = gg[cl] * rsqrtf(vvr[cl] + EPSV);
                float mu = mmu[cl], bb = bta[cl];
                out[(size_t)row * DIMC + cl]       = (c[mi][ni][cc]     - mu) * s + bb;
                out[(size_t)(row + 8) * DIMC + cl] = (c[mi][ni][cc + 2] - mu) * s + bb;
            }
        }
    }
}

// ---------------- launch ----------------
extern "C" void kernel_launch(void* const* d_in, const int* in_sizes, int n_in,
                              void* d_out, int out_size) {
    const float* x      = (const float*)d_in[0];
    const float* text   = (const float*)d_in[1];
    const float* kv_w   = (const float*)d_in[2];
    const float* kv_g   = (const float*)d_in[3];
    const float* kv_b   = (const float*)d_in[4];
    const float* kv_m   = (const float*)d_in[5];
    const float* kv_v   = (const float*)d_in[6];
    const float* q_w    = (const float*)d_in[7];
    const float* q_g    = (const float*)d_in[8];
    const float* q_b    = (const float*)d_in[9];
    const float* q_m    = (const float*)d_in[10];
    const float* q_v    = (const float*)d_in[11];
    const float* proj_w = (const float*)d_in[12];
    const float* proj_g = (const float*)d_in[13];
    const float* proj_b = (const float*)d_in[14];
    const float* proj_m = (const float*)d_in[15];
    const float* proj_v = (const float*)d_in[16];
    const float* biases = (const float*)d_in[17];
    float* out = (float*)d_out;

    k_qproj<<<50, 256>>>(text, q_w, q_g, q_b, q_m, q_v);
    k_kv_mma<<<dim3(HKV / 128, MTOT / 128), 256>>>(x, kv_w, kv_g, kv_b, kv_m, kv_v);
    k_attn<<<dim3(NHEAD, BB), 1024>>>(biases);
    k_proj_mma<<<dim3(2, MTOT / 128), 256>>>(proj_w, proj_g, proj_b, proj_m, proj_v, out);
}